// round 5
// baseline (speedup 1.0000x reference)
#include <cuda_runtime.h>
#include <math.h>

#define T_LEN 32
#define KP    2048
#define BLOCK 256
#define GPC   16                  // threads per column
#define COLS  16                  // columns per block
#define GRID  (KP / COLS)         // 128 blocks

// sp = sqrt(1/32); 0.5/sp^2 = 16 exactly
#define LOG_SP     (-1.7328679513998633f)
#define HALF_L2PI  (0.9189385332046727f)
#define LOG_K      (7.6246189861593985f)
#define C2EXP      (-23.083120654223414f)   // -16 * log2(e)
#define L2E        (1.4426950408889634f)
#define F_INF      (__int_as_float(0x7f800000))

__device__ float g_zs[T_LEN * KP];
__device__ float g_A [T_LEN * KP];
__device__ float g_r [2][KP];

// fast 2^t for t <= 0, branch-free, FMA/ALU pipes only (avoids MUFU bottleneck)
__device__ __forceinline__ float fexp2(float t) {
    t = fmaxf(t, -126.0f);
    float fn = t + 12582912.0f;                 // 1.5 * 2^23 round-to-int trick
    int   n  = __float_as_int(fn) - 0x4B400000;
    float f  = t - (fn - 12582912.0f);          // f in [-0.5, 0.5]
    float p  = 1.3398874e-3f;
    p = fmaf(p, f, 9.6184374e-3f);
    p = fmaf(p, f, 5.5503325e-2f);
    p = fmaf(p, f, 2.4022648e-1f);
    p = fmaf(p, f, 6.9314720e-1f);
    p = fmaf(p, f, 1.0f);
    return __int_as_float(__float_as_int(p) + (n << 23));
}

// Setup: zs = mu + sigma*eps; A[t,k] = -log(sp) - 0.5log2pi - log_q[t,k]; r0
__global__ void setup_kernel(const float* __restrict__ means,
                             const float* __restrict__ log_stds,
                             const float* __restrict__ eps) {
    int idx = blockIdx.x * blockDim.x + threadIdx.x;
    if (idx >= T_LEN * KP) return;
    int t = idx / KP;
    int k = idx - t * KP;
    float mu = means[t];
    float s  = expf(log_stds[t]);
    float e  = eps[idx];
    float z  = fmaf(s, e, mu);
    float zq = (z - mu) / s;
    float lq = fmaf(-0.5f * zq, zq, -logf(s)) - HALF_L2PI;  // proposal logpdf
    g_zs[idx] = z;
    g_A[idx]  = -LOG_SP - HALF_L2PI - lq;
    if (t == 0) {
        float zz = z * 5.656854249492380f;   // z / sp
        g_r[0][k] = fmaf(-0.5f * zz, zz, -LOG_SP) - HALF_L2PI - lq;
    }
}

// One scan step: r_out[k] = x + a_k - 16*mind2_k + log(sum_j u_j * exp(-16*(d2-mind2))) - logK
__global__ void __launch_bounds__(BLOCK) step_kernel(int t) {
    __shared__ float zp[KP];
    __shared__ float uw[KP];
    __shared__ float red[BLOCK / 32];

    const int tid = threadIdx.x;
    const float* __restrict__ r_in  = g_r[(t - 1) & 1];
    float*       __restrict__ r_out = g_r[t & 1];
    const float* __restrict__ zrow  = g_zs + (t - 1) * KP;

    // Load r and z_prev; local max of r
    float lmax = -F_INF;
    float rloc[KP / BLOCK];
    #pragma unroll
    for (int i = 0; i < KP / BLOCK; i++) {
        int j = tid + i * BLOCK;
        float rv = r_in[j];
        rloc[i] = rv;
        zp[j]   = zrow[j];
        lmax    = fmaxf(lmax, rv);
    }
    #pragma unroll
    for (int m = 16; m; m >>= 1)
        lmax = fmaxf(lmax, __shfl_xor_sync(0xffffffffu, lmax, m));
    if ((tid & 31) == 0) red[tid >> 5] = lmax;
    __syncthreads();
    float x = red[0];
    #pragma unroll
    for (int w = 1; w < BLOCK / 32; w++) x = fmaxf(x, red[w]);

    // u_j = exp(r_j - x)
    #pragma unroll
    for (int i = 0; i < KP / BLOCK; i++) {
        int j = tid + i * BLOCK;
        uw[j] = fexp2((rloc[i] - x) * L2E);
    }
    __syncthreads();

    const int k = blockIdx.x * COLS + (tid / GPC);
    const int g = tid & (GPC - 1);
    const float zk = g_zs[t * KP + k];
    const float ak = g_A[t * KP + k];

    // Pass 1: min_j (z_k - z'_j)^2
    float mind2 = F_INF;
    #pragma unroll 8
    for (int i = 0; i < KP / GPC; i++) {
        float d = zk - zp[i * GPC + g];
        mind2 = fminf(mind2, d * d);
    }
    #pragma unroll
    for (int m = GPC / 2; m; m >>= 1)
        mind2 = fminf(mind2, __shfl_xor_sync(0xffffffffu, mind2, m, GPC));

    // Pass 2: S = sum_j u_j * 2^(C2*(d2 - mind2))
    const float negCm = -C2EXP * mind2;
    float S = 0.0f;
    #pragma unroll 8
    for (int i = 0; i < KP / GPC; i++) {
        int j = i * GPC + g;
        float d = zk - zp[j];
        float targ = fmaf(C2EXP, d * d, negCm);
        S = fmaf(uw[j], fexp2(targ), S);
    }
    #pragma unroll
    for (int m = GPC / 2; m; m >>= 1)
        S += __shfl_xor_sync(0xffffffffu, S, m, GPC);

    if (g == 0)
        r_out[k] = x + ak - 16.0f * mind2 + logf(S) - LOG_K;
}

// Final: out = x + y + log(sum_j exp(r_j - x)*exp(L_j - y)) - logK, L_j = logN(0.5; z_j, 1)
__global__ void final_kernel(float* __restrict__ out) {
    __shared__ float sr[KP];
    __shared__ float sL[KP];
    __shared__ float red[32];
    const int tid = threadIdx.x;
    const float* __restrict__ zrow = g_zs + (T_LEN - 1) * KP;
    const float* __restrict__ rv   = g_r[(T_LEN - 1) & 1];

    float lr = -F_INF, lL = -F_INF;
    #pragma unroll
    for (int i = 0; i < KP / 256; i++) {
        int j = tid + i * 256;
        float r = rv[j];
        float z = zrow[j];
        float dd = 0.5f - z;
        float Lv = fmaf(-0.5f * dd, dd, -HALF_L2PI);
        sr[j] = r; sL[j] = Lv;
        lr = fmaxf(lr, r);
        lL = fmaxf(lL, Lv);
    }
    #pragma unroll
    for (int m = 16; m; m >>= 1) {
        lr = fmaxf(lr, __shfl_xor_sync(0xffffffffu, lr, m));
        lL = fmaxf(lL, __shfl_xor_sync(0xffffffffu, lL, m));
    }
    if ((tid & 31) == 0) { red[tid >> 5] = lr; red[8 + (tid >> 5)] = lL; }
    __syncthreads();
    float x = red[0], y = red[8];
    #pragma unroll
    for (int w = 1; w < 8; w++) { x = fmaxf(x, red[w]); y = fmaxf(y, red[8 + w]); }

    float S = 0.0f;
    #pragma unroll
    for (int i = 0; i < KP / 256; i++) {
        int j = tid + i * 256;
        S += fexp2(((sr[j] - x) + (sL[j] - y)) * L2E);
    }
    #pragma unroll
    for (int m = 16; m; m >>= 1)
        S += __shfl_xor_sync(0xffffffffu, S, m);
    if ((tid & 31) == 0) red[16 + (tid >> 5)] = S;
    __syncthreads();
    if (tid == 0) {
        float tot = 0.0f;
        #pragma unroll
        for (int w = 0; w < 8; w++) tot += red[16 + w];
        out[0] = x + y + logf(tot) - LOG_K;
    }
}

extern "C" void kernel_launch(void* const* d_in, const int* in_sizes, int n_in,
                              void* d_out, int out_size) {
    const float* means    = (const float*)d_in[0];
    const float* log_stds = (const float*)d_in[1];
    const float* eps      = (const float*)d_in[2];
    float* out = (float*)d_out;

    setup_kernel<<<(T_LEN * KP + 255) / 256, 256>>>(means, log_stds, eps);
    for (int t = 1; t < T_LEN; t++)
        step_kernel<<<GRID, BLOCK>>>(t);
    final_kernel<<<1, 256>>>(out);
}